// round 1
// baseline (speedup 1.0000x reference)
#include <cuda_runtime.h>
#include <math.h>

#define B_SZ   64
#define IN_SZ  1024
#define OUT_SZ 512
#define T_SZ   512
#define TAU_F  16.0f
#define V_TH   1.0f
#define WIN    32
#define ESTRIDE 1056   // 1024 entries + sentinel + pad

// Scratch (no dynamic allocation allowed)
__device__ float4 g_entries[B_SZ * ESTRIDE];   // 1.06 MB: {k, idx, u, p} sorted by k per batch
__device__ float  g_wT[IN_SZ * OUT_SZ];        // 2 MB transposed weights

// ---------------------------------------------------------------------------
// Kernel 1: per-batch bucket (counting-sort) of input spikes.
// Entry i activates at integer time k = floor(s)+1. Relative to window base
// t0k = (k-1) & ~31 store u = exp((s-t0k)/tau), p = (s-t0k)*u.
// ---------------------------------------------------------------------------
__global__ void prep_kernel(const float* __restrict__ in_spike) {
    __shared__ int hist[258];
    __shared__ int offs[258];
    const int b = blockIdx.x;
    const int i = threadIdx.x;

    if (i < 258) hist[i] = 0;
    __syncthreads();

    const float s = in_spike[b * IN_SZ + i];
    int k = (int)floorf(s) + 1;
    k = max(1, min(k, T_SZ - 1));
    atomicAdd(&hist[k], 1);
    __syncthreads();

    if (i == 0) {
        int acc = 0;
        for (int j = 0; j < 258; j++) { offs[j] = acc; acc += hist[j]; }
    }
    __syncthreads();

    const int pos = atomicAdd(&offs[k], 1);
    const int t0k = (k - 1) & ~(WIN - 1);
    const float rel = s - (float)t0k;              // in [0, 32)
    const float u = expf(rel * (1.0f / TAU_F));    // <= e^2
    const float p = rel * u;
    g_entries[b * ESTRIDE + pos] = make_float4((float)k, (float)i, u, p);
    if (i == 0)
        g_entries[b * ESTRIDE + IN_SZ] = make_float4(1e30f, 0.f, 0.f, 0.f); // sentinel
}

// ---------------------------------------------------------------------------
// Kernel 2: transpose weight [OUT,IN] -> wT [IN,OUT] for coalesced gathers.
// ---------------------------------------------------------------------------
__global__ void transpose_kernel(const float* __restrict__ w) {
    __shared__ float tile[32][33];
    const int i0 = blockIdx.x * 32;  // IN tile
    const int o0 = blockIdx.y * 32;  // OUT tile
    const int tx = threadIdx.x, ty = threadIdx.y;  // 32 x 8
    #pragma unroll
    for (int r = ty; r < 32; r += 8)
        tile[r][tx] = w[(o0 + r) * IN_SZ + i0 + tx];
    __syncthreads();
    #pragma unroll
    for (int r = ty; r < 32; r += 8)
        g_wT[(i0 + r) * OUT_SZ + o0 + tx] = tile[tx][r];
}

// ---------------------------------------------------------------------------
// Kernel 3: running accumulation + first-threshold-crossing.
// One thread per output neuron o; all threads in a block share batch b, so the
// entry-stream walk is control-flow uniform (no divergence).
// V(t) = decay[t-t0] * ((t-t0)*A - B), renormalized by exp(-2) per 32-window.
// ---------------------------------------------------------------------------
__global__ void __launch_bounds__(128) spike_kernel(float* __restrict__ out) {
    __shared__ float decay[WIN + 1];
    const int b = blockIdx.y;
    const int o = blockIdx.x * 128 + threadIdx.x;
    const int tid = threadIdx.x;

    if (tid >= 1 && tid <= WIN)
        decay[tid] = expf(1.0f - (float)tid * (1.0f / TAU_F)) * (1.0f / TAU_F);
    __syncthreads();

    const float4* __restrict__ ent = g_entries + b * ESTRIDE;
    const float*  __restrict__ wcol = g_wT + o;

    float A = 0.0f, Bv = 0.0f;
    int ptr = 0;
    float4 e = ent[0];
    int outT = T_SZ;
    const float D = 0.13533528323661270f;  // exp(-2), window renorm

    for (int t0 = 0; t0 < T_SZ; t0 += WIN) {
        if (t0 > 0) {
            Bv = D * (Bv - (float)WIN * A);
            A  = D * A;
        }
        #pragma unroll 4
        for (int dt = 1; dt <= WIN; dt++) {
            const float tf = (float)(t0 + dt);
            while (e.x <= tf) {              // uniform across block
                const float w = wcol[(int)e.y * OUT_SZ];
                A  = fmaf(w, e.z, A);
                Bv = fmaf(w, e.w, Bv);
                e = ent[++ptr];              // sentinel terminates
            }
            const float volt = decay[dt] * ((float)dt * A - Bv);
            if (volt >= V_TH) outT = min(outT, t0 + dt);
        }
        if (__all_sync(0xffffffffu, outT < T_SZ)) break;  // warp early-exit
    }
    out[b * OUT_SZ + o] = (float)outT;
}

// ---------------------------------------------------------------------------
extern "C" void kernel_launch(void* const* d_in, const int* in_sizes, int n_in,
                              void* d_out, int out_size) {
    const float* in_spike = (const float*)d_in[0];  // [B, IN]
    const float* weight   = (const float*)d_in[1];  // [OUT, IN]
    float* out = (float*)d_out;                     // [B, OUT]
    (void)in_sizes; (void)n_in; (void)out_size;

    prep_kernel<<<B_SZ, IN_SZ>>>(in_spike);
    transpose_kernel<<<dim3(IN_SZ / 32, OUT_SZ / 32), dim3(32, 8)>>>(weight);
    spike_kernel<<<dim3(OUT_SZ / 128, B_SZ), 128>>>(out);
}

// round 3
// speedup vs baseline: 2.9866x; 2.9866x over previous
#include <cuda_runtime.h>
#include <math.h>

#define B_SZ   64
#define IN_SZ  1024
#define OUT_SZ 512
#define T_SZ   512
#define TAU_F  16.0f
#define V_TH   1.0f
#define WIN    32
#define ESTRIDE 1056
#define CH     8          // w-gather prefetch chunk (MLP)

// Scratch (no dynamic allocation allowed)
__device__ float4 g_entries[B_SZ * ESTRIDE];   // {k, idx, u, p} sorted by k per batch
__device__ float  g_wT[IN_SZ * OUT_SZ];        // transposed weights [IN][OUT]

// ---------------------------------------------------------------------------
// Merged prep: blocks [0,64) bucket-sort spikes per batch (parallel scan);
// blocks [64,576) transpose weight [OUT,IN] -> wT[IN,OUT].
// ---------------------------------------------------------------------------
__global__ void __launch_bounds__(1024) prep_kernel(const float* __restrict__ in_spike,
                                                    const float* __restrict__ w) {
    __shared__ int   hist[512];
    __shared__ int   scan[512];
    __shared__ int   offs[512];
    __shared__ float tile[32][33];

    const int bid = blockIdx.x;
    const int i   = threadIdx.x;

    if (bid < B_SZ) {
        const int b = bid;
        if (i < 512) hist[i] = 0;
        __syncthreads();

        const float s = in_spike[b * IN_SZ + i];
        int k = (int)floorf(s) + 1;
        k = max(1, min(k, T_SZ - 1));
        atomicAdd(&hist[k], 1);
        __syncthreads();

        // Hillis-Steele inclusive scan over 512 buckets
        if (i < 512) scan[i] = hist[i];
        __syncthreads();
        #pragma unroll
        for (int d = 1; d < 512; d <<= 1) {
            int v = 0;
            if (i < 512) { v = scan[i]; if (i >= d) v += scan[i - d]; }
            __syncthreads();
            if (i < 512) scan[i] = v;
            __syncthreads();
        }
        if (i < 512) offs[i] = (i == 0) ? 0 : scan[i - 1];  // exclusive
        __syncthreads();

        const int pos = atomicAdd(&offs[k], 1);
        const int t0k = (k - 1) & ~(WIN - 1);
        const float rel = s - (float)t0k;                 // [0, 32)
        const float u = expf(rel * (1.0f / TAU_F));       // <= e^2
        const float p = rel * u;
        g_entries[b * ESTRIDE + pos] = make_float4((float)k, (float)i, u, p);
    } else {
        const int tb = bid - B_SZ;                // 0..511 tiles
        const int i0 = (tb & 31) * 32;            // IN tile
        const int o0 = (tb >> 5) * 32;            // OUT tile
        const int tx = i & 31, ty = i >> 5;       // 32 x 32
        tile[ty][tx] = w[(o0 + ty) * IN_SZ + i0 + tx];
        __syncthreads();
        g_wT[(i0 + ty) * OUT_SZ + o0 + tx] = tile[tx][ty];
    }
}

// ---------------------------------------------------------------------------
// Spike kernel: entry-major counted loop with double-buffered w prefetch.
// All 128 threads of a block share batch b -> entry stream is uniform.
// V(t) = decay[dt] * (dt*A - B) in the frame of window t0=(t-1)&~31;
// renormalize (A,B) by exp(-2) at each window boundary.
// ---------------------------------------------------------------------------
__global__ void __launch_bounds__(128) spike_kernel(float* __restrict__ out) {
    __shared__ float4 sent[IN_SZ];     // 16 KB staged entries
    __shared__ float  sdecay[WIN + 1];

    const int b   = blockIdx.y;
    const int o   = blockIdx.x * 128 + threadIdx.x;
    const int tid = threadIdx.x;

    const float4* __restrict__ ge = g_entries + b * ESTRIDE;
    for (int j = tid; j < IN_SZ; j += 128) sent[j] = ge[j];
    if (tid >= 1 && tid <= WIN)
        sdecay[tid] = expf(1.0f - (float)tid * (1.0f / TAU_F)) * (1.0f / TAU_F);
    __syncthreads();

    const float* __restrict__ wcol = g_wT + o;
    const float D = 0.13533528323661270f;  // exp(-2)

    float A = 0.0f, Bv = 0.0f;
    int t_cur = 1;          // next time index to evaluate
    int outT = T_SZ;

    // prime first chunk of w gathers
    float wc[CH];
    #pragma unroll
    for (int q = 0; q < CH; q++)
        wc[q] = wcol[((int)sent[q].y) * OUT_SZ];

    bool done = false;
    for (int c = 0; c < IN_SZ / CH; c++) {
        float wn[CH];
        if (c + 1 < IN_SZ / CH) {
            #pragma unroll
            for (int q = 0; q < CH; q++)
                wn[q] = wcol[((int)sent[(c + 1) * CH + q].y) * OUT_SZ];
        }
        #pragma unroll
        for (int q = 0; q < CH; q++) {
            const float4 e = sent[c * CH + q];
            const int k = (int)e.x;
            while (t_cur < k) {                   // advance evals up to k-1
                const int dt = ((t_cur - 1) & (WIN - 1)) + 1;
                const float volt = sdecay[dt] * ((float)dt * A - Bv);
                if (volt >= V_TH) outT = min(outT, t_cur);
                if (dt == WIN) { Bv = D * (Bv - (float)WIN * A); A = D * A; }
                t_cur++;
            }
            A  = fmaf(wc[q], e.z, A);
            Bv = fmaf(wc[q], e.w, Bv);
        }
        #pragma unroll
        for (int q = 0; q < CH; q++) wc[q] = wn[q];
        if (__all_sync(0xffffffffu, outT < T_SZ)) { done = true; break; }
    }

    if (!done) {
        while (t_cur < T_SZ) {                    // tail: no more inputs
            const int dt = ((t_cur - 1) & (WIN - 1)) + 1;
            const float volt = sdecay[dt] * ((float)dt * A - Bv);
            if (volt >= V_TH) outT = min(outT, t_cur);
            if (dt == WIN) {
                Bv = D * (Bv - (float)WIN * A); A = D * A;
                if (__all_sync(0xffffffffu, outT < T_SZ)) break;
            }
            t_cur++;
        }
    }
    out[b * OUT_SZ + o] = (float)outT;
}

// ---------------------------------------------------------------------------
extern "C" void kernel_launch(void* const* d_in, const int* in_sizes, int n_in,
                              void* d_out, int out_size) {
    const float* in_spike = (const float*)d_in[0];  // [B, IN]
    const float* weight   = (const float*)d_in[1];  // [OUT, IN]
    float* out = (float*)d_out;                     // [B, OUT]
    (void)in_sizes; (void)n_in; (void)out_size;

    prep_kernel<<<B_SZ + (IN_SZ / 32) * (OUT_SZ / 32), 1024>>>(in_spike, weight);
    spike_kernel<<<dim3(OUT_SZ / 128, B_SZ), 128>>>(out);
}

// round 4
// speedup vs baseline: 5.5106x; 1.8451x over previous
#include <cuda_runtime.h>
#include <math.h>

#define B_SZ   64
#define IN_SZ  1024
#define OUT_SZ 512
#define T_SZ   512
#define TAU_F  16.0f
#define V_TH   1.0f
#define WIN    32
#define NW     16          // T / WIN
#define ESTRIDE 1056
#define CH     8           // w-gather prefetch chunk (MLP)
#define SENT_MAX 512       // max entries per window staged in smem

// Scratch (no dynamic allocation allowed)
__device__ float4 g_entries[B_SZ * ESTRIDE];       // {k, idx, u, p} sorted by k per batch
__device__ float  g_wT[IN_SZ * OUT_SZ];            // transposed weights [IN][OUT]
__device__ int    g_wstart[B_SZ * (NW + 1)];       // per-batch window entry offsets
__device__ float2 g_P[B_SZ * NW * OUT_SZ];         // per-window partial sums {PA, PB}

// ---------------------------------------------------------------------------
// Prep: blocks [0,64) bucket-sort spikes per batch (parallel scan) + window
// offsets + output init; blocks [64,576) transpose weight -> wT[IN][OUT].
// ---------------------------------------------------------------------------
__global__ void __launch_bounds__(1024) prep_kernel(const float* __restrict__ in_spike,
                                                    const float* __restrict__ w,
                                                    float* __restrict__ out) {
    __shared__ int   hist[512];
    __shared__ int   scan[512];
    __shared__ int   offs[512];
    __shared__ float tile[32][33];

    const int bid = blockIdx.x;
    const int i   = threadIdx.x;

    if (bid < B_SZ) {
        const int b = bid;
        if (i < 512) { hist[i] = 0; out[b * OUT_SZ + i] = 512.0f; }  // init for atomicMin
        __syncthreads();

        const float s = in_spike[b * IN_SZ + i];
        int k = (int)floorf(s) + 1;
        k = max(1, min(k, T_SZ - 1));
        atomicAdd(&hist[k], 1);
        __syncthreads();

        // Hillis-Steele inclusive scan over 512 buckets
        if (i < 512) scan[i] = hist[i];
        __syncthreads();
        #pragma unroll
        for (int d = 1; d < 512; d <<= 1) {
            int v = 0;
            if (i < 512) { v = scan[i]; if (i >= d) v += scan[i - d]; }
            __syncthreads();
            if (i < 512) scan[i] = v;
            __syncthreads();
        }
        if (i < 512) offs[i] = (i == 0) ? 0 : scan[i - 1];           // exclusive
        // window start offsets: entries with k <= 32w precede window w
        if (i <= NW) g_wstart[b * (NW + 1) + i] = (i == NW) ? IN_SZ : scan[i * WIN];
        __syncthreads();

        const int pos = atomicAdd(&offs[k], 1);
        const int t0k = (k - 1) & ~(WIN - 1);
        const float rel = s - (float)t0k;                 // [0, 32)
        const float u = expf(rel * (1.0f / TAU_F));       // <= e^2
        const float p = rel * u;
        g_entries[b * ESTRIDE + pos] = make_float4((float)k, (float)i, u, p);
    } else {
        const int tb = bid - B_SZ;
        const int i0 = (tb & 31) * 32;
        const int o0 = (tb >> 5) * 32;
        const int tx = i & 31, ty = i >> 5;               // 32 x 32
        tile[ty][tx] = w[(o0 + ty) * IN_SZ + i0 + tx];
        __syncthreads();
        g_wT[(i0 + ty) * OUT_SZ + o0 + tx] = tile[tx][ty];
    }
}

// ---------------------------------------------------------------------------
// Phase 2: per-window partial sums. Grid (OUT/128, B, NW). Branch-free
// chunk-prefetched FMA stream over this window's entries.
//   PA = sum w[o,idx]*u,  PB = sum w[o,idx]*p   (window-local frame)
// ---------------------------------------------------------------------------
__global__ void __launch_bounds__(128) partial_kernel() {
    __shared__ float4 sent[SENT_MAX];
    const int W = blockIdx.z, b = blockIdx.y;
    const int tid = threadIdx.x;
    const int o = blockIdx.x * 128 + tid;

    const int start = g_wstart[b * (NW + 1) + W];
    const int count = g_wstart[b * (NW + 1) + W + 1] - start;
    const int padded = (count + CH - 1) & ~(CH - 1);

    const float4* __restrict__ ge = g_entries + b * ESTRIDE + start;
    for (int j = tid; j < padded; j += 128)
        sent[j] = (j < count) ? ge[j] : make_float4(1e9f, 0.f, 0.f, 0.f);
    __syncthreads();

    const float* __restrict__ wcol = g_wT + o;
    float PA = 0.0f, PB = 0.0f;

    if (count > 0) {
        float wc[CH];
        #pragma unroll
        for (int q = 0; q < CH; q++) wc[q] = wcol[((int)sent[q].y) * OUT_SZ];
        const int nch = padded / CH;
        for (int c = 0; c < nch; c++) {
            float wn[CH];
            if (c + 1 < nch) {
                #pragma unroll
                for (int q = 0; q < CH; q++)
                    wn[q] = wcol[((int)sent[(c + 1) * CH + q].y) * OUT_SZ];
            }
            #pragma unroll
            for (int q = 0; q < CH; q++) {
                const float4 e = sent[c * CH + q];        // pads have u=p=0
                PA = fmaf(wc[q], e.z, PA);
                PB = fmaf(wc[q], e.w, PB);
            }
            #pragma unroll
            for (int q = 0; q < CH; q++) wc[q] = wn[q];
        }
    }
    g_P[(b * NW + W) * OUT_SZ + o] = make_float2(PA, PB);
}

// ---------------------------------------------------------------------------
// Phase 3: per-window evaluation. Reconstruct (A,B) at window start from
// earlier window partials (A = sum D^d*PA, B = sum D^d*(PB - 32d*PA)),
// then interleaved entry/eval walk over the window's 32 time steps.
// First crossing recorded via atomicMin on positive-float bit pattern.
// ---------------------------------------------------------------------------
__global__ void __launch_bounds__(128) window_kernel(float* __restrict__ out) {
    __shared__ float4 sent[SENT_MAX];
    __shared__ float  sdecay[WIN + 1];
    const int W = blockIdx.z, b = blockIdx.y;
    const int tid = threadIdx.x;
    const int o = blockIdx.x * 128 + tid;

    if (tid >= 1 && tid <= WIN)
        sdecay[tid] = expf(1.0f - (float)tid * (1.0f / TAU_F)) * (1.0f / TAU_F);

    const int start = g_wstart[b * (NW + 1) + W];
    const int count = g_wstart[b * (NW + 1) + W + 1] - start;
    const int padded = (count + CH - 1) & ~(CH - 1);

    const float4* __restrict__ ge = g_entries + b * ESTRIDE + start;
    for (int j = tid; j < padded; j += 128)
        sent[j] = (j < count) ? ge[j] : make_float4(1e9f, 0.f, 0.f, 0.f);
    __syncthreads();

    const float* __restrict__ wcol = g_wT + o;
    const float D = 0.13533528323661270f;   // exp(-2) per-window decay

    // Prefix from earlier windows: predicated unroll -> MLP up to 15
    float A = 0.0f, Bv = 0.0f, dp = 1.0f;
    #pragma unroll
    for (int j = 1; j < NW; j++) {
        dp *= D;
        const int w = W - j;
        if (w >= 0) {
            const float2 P = g_P[(b * NW + w) * OUT_SZ + o];
            A  = fmaf(dp, P.x, A);
            Bv = fmaf(dp, P.y - (float)(WIN * j) * P.x, Bv);
        }
    }

    int t_dt = 1;          // dt within window, 1..32
    int cand = 1000;       // local first-crossing dt

    if (count > 0) {
        float wc[CH];
        #pragma unroll
        for (int q = 0; q < CH; q++) wc[q] = wcol[((int)sent[q].y) * OUT_SZ];
        const int nch = padded / CH;
        for (int c = 0; c < nch; c++) {
            float wn[CH];
            if (c + 1 < nch) {
                #pragma unroll
                for (int q = 0; q < CH; q++)
                    wn[q] = wcol[((int)sent[(c + 1) * CH + q].y) * OUT_SZ];
            }
            #pragma unroll
            for (int q = 0; q < CH; q++) {
                const float4 e = sent[c * CH + q];
                const int kdt = (int)e.x - W * WIN;       // sentinel -> huge
                while (t_dt < kdt && t_dt <= WIN) {       // uniform across block
                    const float volt = sdecay[t_dt] * ((float)t_dt * A - Bv);
                    if (volt >= V_TH) cand = min(cand, t_dt);
                    t_dt++;
                }
                A  = fmaf(wc[q], e.z, A);
                Bv = fmaf(wc[q], e.w, Bv);
            }
            #pragma unroll
            for (int q = 0; q < CH; q++) wc[q] = wn[q];
        }
    }
    while (t_dt <= WIN) {                                 // tail / empty window
        const float volt = sdecay[t_dt] * ((float)t_dt * A - Bv);
        if (volt >= V_TH) cand = min(cand, t_dt);
        t_dt++;
    }

    if (cand <= WIN)
        atomicMin((int*)out + b * OUT_SZ + o,
                  __float_as_int((float)(W * WIN + cand)));
}

// ---------------------------------------------------------------------------
extern "C" void kernel_launch(void* const* d_in, const int* in_sizes, int n_in,
                              void* d_out, int out_size) {
    const float* in_spike = (const float*)d_in[0];  // [B, IN]
    const float* weight   = (const float*)d_in[1];  // [OUT, IN]
    float* out = (float*)d_out;                     // [B, OUT]
    (void)in_sizes; (void)n_in; (void)out_size;

    prep_kernel<<<B_SZ + (IN_SZ / 32) * (OUT_SZ / 32), 1024>>>(in_spike, weight, out);
    partial_kernel<<<dim3(OUT_SZ / 128, B_SZ, NW), 128>>>();
    window_kernel<<<dim3(OUT_SZ / 128, B_SZ, NW), 128>>>(out);
}

// round 6
// speedup vs baseline: 7.4922x; 1.3596x over previous
#include <cuda_runtime.h>
#include <math.h>

#define B_SZ   64
#define IN_SZ  1024
#define OUT_SZ 512
#define T_SZ   512
#define TAU_F  16.0f
#define V_TH   1.0f
#define WIN    32
#define NWE    8           // windows that can contain entries (spikes < 256)
#define NW     16          // total windows
#define ESTRIDE 1056
#define CH     8           // w-gather prefetch chunk (MLP)
#define SENT_MAX 512

// Scratch (no dynamic allocation allowed)
__device__ float4 g_entries[B_SZ * ESTRIDE];        // {k, idx, u, p} sorted per batch
__device__ float  g_wT[IN_SZ * OUT_SZ];             // transposed weights [IN][OUT]
__device__ int    g_wstart[B_SZ * (NWE + 1)];       // per-batch window entry offsets
__device__ float2 g_P[B_SZ * NWE * OUT_SZ];         // per-window partials {PA, PB}
__device__ float2 g_S[B_SZ * NWE * OUT_SZ];         // per-window start state {A, B}

// ---------------------------------------------------------------------------
// Prep: blocks [0,64) bucket-sort spikes per batch (warp-shuffle scan) +
// window offsets + output init; blocks [64,576) transpose weight.
// ---------------------------------------------------------------------------
__global__ void __launch_bounds__(1024) prep_kernel(const float* __restrict__ in_spike,
                                                    const float* __restrict__ w,
                                                    float* __restrict__ out) {
    __shared__ int   hist[512];
    __shared__ int   scanv[512];
    __shared__ int   offs[512];
    __shared__ int   wsum[16];
    __shared__ float tile[32][33];

    const int bid = blockIdx.x;
    const int i   = threadIdx.x;

    if (bid < B_SZ) {
        const int b = bid;
        if (i < 512) { hist[i] = 0; out[b * OUT_SZ + i] = 512.0f; }  // init for atomicMin
        __syncthreads();

        const float s = in_spike[b * IN_SZ + i];
        int k = (int)floorf(s) + 1;
        k = max(1, min(k, T_SZ - 1));
        atomicAdd(&hist[k], 1);
        __syncthreads();

        int h0 = 0, incl = 0;
        if (i < 512) {
            h0 = hist[i]; incl = h0;
            #pragma unroll
            for (int d = 1; d < 32; d <<= 1) {
                int n = __shfl_up_sync(0xffffffffu, incl, d);
                if ((i & 31) >= d) incl += n;
            }
            if ((i & 31) == 31) wsum[i >> 5] = incl;
        }
        __syncthreads();
        if (i < 16) {
            int s2 = wsum[i];
            #pragma unroll
            for (int d = 1; d < 16; d <<= 1) {
                int n = __shfl_up_sync(0x0000ffffu, s2, d);
                if (i >= d) s2 += n;
            }
            wsum[i] = s2;
        }
        __syncthreads();
        if (i < 512) {
            const int wrp = i >> 5;
            if (wrp > 0) incl += wsum[wrp - 1];
            scanv[i] = incl;          // inclusive scan
            offs[i]  = incl - h0;     // exclusive
        }
        __syncthreads();
        if (i <= NWE) g_wstart[b * (NWE + 1) + i] = scanv[i * WIN];  // scanv[0]=0

        const int pos = atomicAdd(&offs[k], 1);
        const int t0k = (k - 1) & ~(WIN - 1);
        const float rel = s - (float)t0k;              // [0, 32)
        const float u = expf(rel * (1.0f / TAU_F));    // <= e^2
        const float p = rel * u;
        g_entries[b * ESTRIDE + pos] = make_float4((float)k, (float)i, u, p);
    } else {
        const int tb = bid - B_SZ;
        const int i0 = (tb & 31) * 32;
        const int o0 = (tb >> 5) * 32;
        const int tx = i & 31, ty = i >> 5;            // 32 x 32
        tile[ty][tx] = w[(o0 + ty) * IN_SZ + i0 + tx];
        __syncthreads();
        g_wT[(i0 + ty) * OUT_SZ + o0 + tx] = tile[tx][ty];
    }
}

// ---------------------------------------------------------------------------
// Phase 2: per-window partial sums, 2 outputs/thread (float2 weight loads).
// Grid (OUT/256, B, NWE).
// ---------------------------------------------------------------------------
__global__ void __launch_bounds__(128) partial_kernel() {
    __shared__ float4 sent[SENT_MAX];
    const int W = blockIdx.z, b = blockIdx.y;
    const int tid = threadIdx.x;

    const int start = g_wstart[b * (NWE + 1) + W];
    const int count = g_wstart[b * (NWE + 1) + W + 1] - start;
    const int padded = (count + CH - 1) & ~(CH - 1);

    const float4* __restrict__ ge = g_entries + b * ESTRIDE + start;
    for (int j = tid; j < padded; j += 128)
        sent[j] = (j < count) ? ge[j] : make_float4(1e9f, 0.f, 0.f, 0.f);
    __syncthreads();

    const float2* __restrict__ wp = (const float2*)g_wT + blockIdx.x * 128 + tid;
    float PA0 = 0.f, PB0 = 0.f, PA1 = 0.f, PB1 = 0.f;

    if (count > 0) {
        float2 wc[CH];
        #pragma unroll
        for (int q = 0; q < CH; q++) wc[q] = wp[((int)sent[q].y) << 8];
        const int nch = padded / CH;
        for (int c = 0; c < nch; c++) {
            float2 wn[CH];
            if (c + 1 < nch) {
                #pragma unroll
                for (int q = 0; q < CH; q++)
                    wn[q] = wp[((int)sent[(c + 1) * CH + q].y) << 8];
            }
            #pragma unroll
            for (int q = 0; q < CH; q++) {
                const float4 e = sent[c * CH + q];       // pads have u=p=0
                PA0 = fmaf(wc[q].x, e.z, PA0); PB0 = fmaf(wc[q].x, e.w, PB0);
                PA1 = fmaf(wc[q].y, e.z, PA1); PB1 = fmaf(wc[q].y, e.w, PB1);
            }
            #pragma unroll
            for (int q = 0; q < CH; q++) wc[q] = wn[q];
        }
    }
    const int o = blockIdx.x * 256 + 2 * tid;
    *(float4*)&g_P[(b * NWE + W) * OUT_SZ + o] = make_float4(PA0, PB0, PA1, PB1);
}

// ---------------------------------------------------------------------------
// Phase 3a: per-(b,o) window-prefix scan: A' = D(A+PA), B' = D(B+PB) - 32 A'.
// Writes start state for windows 0..7; directly evaluates entry-free
// windows 8..15 (V = decay[dt]*(dt*A - B)) with first-crossing atomicMin.
// ---------------------------------------------------------------------------
__global__ void __launch_bounds__(128) scan_kernel(float* __restrict__ out) {
    __shared__ float sdecay[WIN + 1];
    const int b = blockIdx.y;
    const int o = blockIdx.x * 128 + threadIdx.x;
    if (threadIdx.x >= 1 && threadIdx.x <= WIN)
        sdecay[threadIdx.x] = expf(1.0f - (float)threadIdx.x * (1.0f / TAU_F)) * (1.0f / TAU_F);
    __syncthreads();

    float2 P[NWE];
    #pragma unroll
    for (int w = 0; w < NWE; w++) P[w] = g_P[(b * NWE + w) * OUT_SZ + o];

    const float D = 0.13533528323661270f;   // exp(-2)
    float As = 0.f, Bs = 0.f;
    #pragma unroll
    for (int W = 0; W < NWE; W++) {
        if (W > 0) {
            As = D * (As + P[W - 1].x);
            Bs = D * (Bs + P[W - 1].y) - (float)WIN * As;
        }
        g_S[(b * NWE + W) * OUT_SZ + o] = make_float2(As, Bs);
    }
    int found = 0, result = 0;
    for (int W = NWE; W < NW && !found; W++) {
        const float pa = (W == NWE) ? P[NWE - 1].x : 0.f;
        const float pb = (W == NWE) ? P[NWE - 1].y : 0.f;
        As = D * (As + pa);
        Bs = D * (Bs + pb) - (float)WIN * As;
        int c = 1000;
        #pragma unroll
        for (int dt = 1; dt <= WIN; dt++) {
            const float volt = sdecay[dt] * ((float)dt * As - Bs);
            if (volt >= V_TH) c = min(c, dt);
        }
        if (c <= WIN) { found = 1; result = W * WIN + c; }
    }
    if (found)
        atomicMin((int*)out + b * OUT_SZ + o, __float_as_int((float)result));
}

// ---------------------------------------------------------------------------
// Phase 3b: per-window evaluation for entry windows 0..7, 2 outputs/thread.
// Start state read as one float4; interleaved entry/eval walk; atomicMin.
// ---------------------------------------------------------------------------
__global__ void __launch_bounds__(128) window_kernel(float* __restrict__ out) {
    __shared__ float4 sent[SENT_MAX];
    __shared__ float  sdecay[WIN + 1];
    const int W = blockIdx.z, b = blockIdx.y;
    const int tid = threadIdx.x;
    const int o = blockIdx.x * 256 + 2 * tid;

    if (tid >= 1 && tid <= WIN)
        sdecay[tid] = expf(1.0f - (float)tid * (1.0f / TAU_F)) * (1.0f / TAU_F);

    const int start = g_wstart[b * (NWE + 1) + W];
    const int count = g_wstart[b * (NWE + 1) + W + 1] - start;
    const int padded = (count + CH - 1) & ~(CH - 1);

    const float4* __restrict__ ge = g_entries + b * ESTRIDE + start;
    for (int j = tid; j < padded; j += 128)
        sent[j] = (j < count) ? ge[j] : make_float4(1e9f, 0.f, 0.f, 0.f);
    __syncthreads();

    const float4 S = *(const float4*)&g_S[(b * NWE + W) * OUT_SZ + o];
    float A0 = S.x, B0 = S.y, A1 = S.z, B1 = S.w;

    const float2* __restrict__ wp = (const float2*)g_wT + blockIdx.x * 128 + tid;

    int t_dt = 1, cand0 = 1000, cand1 = 1000;
    if (count > 0) {
        float2 wc[CH];
        #pragma unroll
        for (int q = 0; q < CH; q++) wc[q] = wp[((int)sent[q].y) << 8];
        const int nch = padded / CH;
        for (int c = 0; c < nch; c++) {
            float2 wn[CH];
            if (c + 1 < nch) {
                #pragma unroll
                for (int q = 0; q < CH; q++)
                    wn[q] = wp[((int)sent[(c + 1) * CH + q].y) << 8];
            }
            #pragma unroll
            for (int q = 0; q < CH; q++) {
                const float4 e = sent[c * CH + q];
                const int kdt = (int)e.x - W * WIN;       // sentinel -> huge
                while (t_dt < kdt && t_dt <= WIN) {       // uniform across block
                    const float dec = sdecay[t_dt];
                    const float tf = (float)t_dt;
                    if (dec * (tf * A0 - B0) >= V_TH) cand0 = min(cand0, t_dt);
                    if (dec * (tf * A1 - B1) >= V_TH) cand1 = min(cand1, t_dt);
                    t_dt++;
                }
                A0 = fmaf(wc[q].x, e.z, A0); B0 = fmaf(wc[q].x, e.w, B0);
                A1 = fmaf(wc[q].y, e.z, A1); B1 = fmaf(wc[q].y, e.w, B1);
            }
            #pragma unroll
            for (int q = 0; q < CH; q++) wc[q] = wn[q];
            if (__all_sync(0xffffffffu, (cand0 < 1000) & (cand1 < 1000))) break;
        }
    }
    while (t_dt <= WIN) {                                 // tail / empty window
        const float dec = sdecay[t_dt];
        const float tf = (float)t_dt;
        if (dec * (tf * A0 - B0) >= V_TH) cand0 = min(cand0, t_dt);
        if (dec * (tf * A1 - B1) >= V_TH) cand1 = min(cand1, t_dt);
        t_dt++;
    }
    int* ob = (int*)out + b * OUT_SZ;
    const float Wbase = (float)(W * WIN);
    if (cand0 <= WIN) atomicMin(ob + o,     __float_as_int(Wbase + (float)cand0));
    if (cand1 <= WIN) atomicMin(ob + o + 1, __float_as_int(Wbase + (float)cand1));
}

// ---------------------------------------------------------------------------
extern "C" void kernel_launch(void* const* d_in, const int* in_sizes, int n_in,
                              void* d_out, int out_size) {
    const float* in_spike = (const float*)d_in[0];  // [B, IN]
    const float* weight   = (const float*)d_in[1];  // [OUT, IN]
    float* out = (float*)d_out;                     // [B, OUT]
    (void)in_sizes; (void)n_in; (void)out_size;

    prep_kernel<<<B_SZ + (IN_SZ / 32) * (OUT_SZ / 32), 1024>>>(in_spike, weight, out);
    partial_kernel<<<dim3(OUT_SZ / 256, B_SZ, NWE), 128>>>();
    scan_kernel<<<dim3(OUT_SZ / 128, B_SZ), 128>>>(out);
    window_kernel<<<dim3(OUT_SZ / 256, B_SZ, NWE), 128>>>(out);
}

// round 7
// speedup vs baseline: 7.7648x; 1.0364x over previous
#include <cuda_runtime.h>
#include <math.h>

#define B_SZ   64
#define IN_SZ  1024
#define OUT_SZ 512
#define T_SZ   512
#define TAU_F  16.0f
#define V_TH   1.0f
#define WIN    32
#define NWE    8           // windows that can contain entries (spikes < 256)
#define NW     16          // total windows
#define ESTRIDE 1056
#define CH     8           // w-gather prefetch chunk (MLP)
#define SENT_MAX 512

// Scratch (no dynamic allocation allowed)
__device__ float4 g_entries[B_SZ * ESTRIDE];        // {k, idx, u, p} sorted per batch
__device__ float  g_wT[IN_SZ * OUT_SZ];             // transposed weights [IN][OUT]
__device__ int    g_wstart[B_SZ * (NWE + 1)];       // per-batch window entry offsets
__device__ float2 g_P[B_SZ * NWE * OUT_SZ];         // per-window partials {PA, PB}
__device__ float2 g_S[B_SZ * NWE * OUT_SZ];         // per-window start state {A, B}

// ---------------------------------------------------------------------------
// Prep: blocks [0,64) bucket-sort spikes per batch (warp-shuffle scan) +
// window offsets + output init; blocks [64,576) transpose weight.
// ---------------------------------------------------------------------------
__global__ void __launch_bounds__(1024) prep_kernel(const float* __restrict__ in_spike,
                                                    const float* __restrict__ w,
                                                    float* __restrict__ out) {
    __shared__ int   hist[512];
    __shared__ int   scanv[512];
    __shared__ int   offs[512];
    __shared__ int   wsum[16];
    __shared__ float tile[32][33];

    const int bid = blockIdx.x;
    const int i   = threadIdx.x;

    if (bid < B_SZ) {
        const int b = bid;
        if (i < 512) { hist[i] = 0; out[b * OUT_SZ + i] = 512.0f; }  // init for atomicMin
        __syncthreads();

        const float s = in_spike[b * IN_SZ + i];
        int k = (int)floorf(s) + 1;
        k = max(1, min(k, T_SZ - 1));
        atomicAdd(&hist[k], 1);
        __syncthreads();

        int h0 = 0, incl = 0;
        if (i < 512) {
            h0 = hist[i]; incl = h0;
            #pragma unroll
            for (int d = 1; d < 32; d <<= 1) {
                int n = __shfl_up_sync(0xffffffffu, incl, d);
                if ((i & 31) >= d) incl += n;
            }
            if ((i & 31) == 31) wsum[i >> 5] = incl;
        }
        __syncthreads();
        if (i < 16) {
            int s2 = wsum[i];
            #pragma unroll
            for (int d = 1; d < 16; d <<= 1) {
                int n = __shfl_up_sync(0x0000ffffu, s2, d);
                if (i >= d) s2 += n;
            }
            wsum[i] = s2;
        }
        __syncthreads();
        if (i < 512) {
            const int wrp = i >> 5;
            if (wrp > 0) incl += wsum[wrp - 1];
            scanv[i] = incl;          // inclusive scan
            offs[i]  = incl - h0;     // exclusive
        }
        __syncthreads();
        if (i <= NWE) g_wstart[b * (NWE + 1) + i] = scanv[i * WIN];  // scanv[0]=0

        const int pos = atomicAdd(&offs[k], 1);
        const int t0k = (k - 1) & ~(WIN - 1);
        const float rel = s - (float)t0k;              // [0, 32)
        const float u = expf(rel * (1.0f / TAU_F));    // <= e^2
        const float p = rel * u;
        g_entries[b * ESTRIDE + pos] = make_float4((float)k, (float)i, u, p);
    } else {
        const int tb = bid - B_SZ;
        const int i0 = (tb & 31) * 32;
        const int o0 = (tb >> 5) * 32;
        const int tx = i & 31, ty = i >> 5;            // 32 x 32
        tile[ty][tx] = w[(o0 + ty) * IN_SZ + i0 + tx];
        __syncthreads();
        g_wT[(i0 + ty) * OUT_SZ + o0 + tx] = tile[tx][ty];
    }
}

// ---------------------------------------------------------------------------
// Phase 2: per-window partial sums, 4 outputs/thread (float4 weight loads).
// Grid (NWE, B). One 128-thread block covers all 512 outputs.
// ---------------------------------------------------------------------------
__global__ void __launch_bounds__(128) partial_kernel() {
    __shared__ float4 sent[SENT_MAX];
    const int W = blockIdx.x, b = blockIdx.y;
    const int tid = threadIdx.x;

    const int start = g_wstart[b * (NWE + 1) + W];
    const int count = g_wstart[b * (NWE + 1) + W + 1] - start;
    const int padded = (count + CH - 1) & ~(CH - 1);

    const float4* __restrict__ ge = g_entries + b * ESTRIDE + start;
    for (int j = tid; j < padded; j += 128)
        sent[j] = (j < count) ? ge[j] : make_float4(1e9f, 0.f, 0.f, 0.f);
    __syncthreads();

    const float4* __restrict__ wp = (const float4*)g_wT + tid;   // w[idx][4tid..4tid+3]
    float PA0 = 0.f, PB0 = 0.f, PA1 = 0.f, PB1 = 0.f;
    float PA2 = 0.f, PB2 = 0.f, PA3 = 0.f, PB3 = 0.f;

    if (count > 0) {
        float4 wc[CH];
        #pragma unroll
        for (int q = 0; q < CH; q++) wc[q] = wp[((int)sent[q].y) << 7];
        const int nch = padded / CH;
        for (int c = 0; c < nch; c++) {
            float4 wn[CH];
            if (c + 1 < nch) {
                #pragma unroll
                for (int q = 0; q < CH; q++)
                    wn[q] = wp[((int)sent[(c + 1) * CH + q].y) << 7];
            }
            #pragma unroll
            for (int q = 0; q < CH; q++) {
                const float4 e = sent[c * CH + q];       // pads have u=p=0
                PA0 = fmaf(wc[q].x, e.z, PA0); PB0 = fmaf(wc[q].x, e.w, PB0);
                PA1 = fmaf(wc[q].y, e.z, PA1); PB1 = fmaf(wc[q].y, e.w, PB1);
                PA2 = fmaf(wc[q].z, e.z, PA2); PB2 = fmaf(wc[q].z, e.w, PB2);
                PA3 = fmaf(wc[q].w, e.z, PA3); PB3 = fmaf(wc[q].w, e.w, PB3);
            }
            #pragma unroll
            for (int q = 0; q < CH; q++) wc[q] = wn[q];
        }
    }
    float2* Pp = &g_P[(b * NWE + W) * OUT_SZ + 4 * tid];
    *(float4*)(Pp)     = make_float4(PA0, PB0, PA1, PB1);
    *(float4*)(Pp + 2) = make_float4(PA2, PB2, PA3, PB3);
}

// ---------------------------------------------------------------------------
// Phase 3a: per-(b,o) window-prefix scan: A' = D(A+PA), B' = D(B+PB) - 32 A'.
// Writes start state for windows 0..7; directly evaluates entry-free
// windows 8..15 via threshold table, first crossing -> atomicMin.
// ---------------------------------------------------------------------------
__global__ void __launch_bounds__(128) scan_kernel(float* __restrict__ out) {
    __shared__ float sthresh[WIN + 1];
    const int b = blockIdx.y;
    const int o = blockIdx.x * 128 + threadIdx.x;
    if (threadIdx.x >= 1 && threadIdx.x <= WIN) {
        const float dec = expf(1.0f - (float)threadIdx.x * (1.0f / TAU_F)) * (1.0f / TAU_F);
        sthresh[threadIdx.x] = V_TH / dec;
    }
    __syncthreads();

    float2 P[NWE];
    #pragma unroll
    for (int w = 0; w < NWE; w++) P[w] = g_P[(b * NWE + w) * OUT_SZ + o];

    const float D = 0.13533528323661270f;   // exp(-2)
    float As = 0.f, Bs = 0.f;
    #pragma unroll
    for (int W = 0; W < NWE; W++) {
        if (W > 0) {
            As = D * (As + P[W - 1].x);
            Bs = D * (Bs + P[W - 1].y) - (float)WIN * As;
        }
        g_S[(b * NWE + W) * OUT_SZ + o] = make_float2(As, Bs);
    }
    int found = 0, result = 0;
    for (int W = NWE; W < NW && !found; W++) {
        const float pa = (W == NWE) ? P[NWE - 1].x : 0.f;
        const float pb = (W == NWE) ? P[NWE - 1].y : 0.f;
        As = D * (As + pa);
        Bs = D * (Bs + pb) - (float)WIN * As;
        int c = 1000;
        #pragma unroll
        for (int dt = 1; dt <= WIN; dt++) {
            if (fmaf((float)dt, As, -Bs) >= sthresh[dt]) c = min(c, dt);
        }
        if (c <= WIN) { found = 1; result = W * WIN + c; }
    }
    if (found)
        atomicMin((int*)out + b * OUT_SZ + o, __float_as_int((float)result));
}

// ---------------------------------------------------------------------------
// Phase 3b: per-window evaluation for entry windows 0..7, 4 outputs/thread.
// Entries staged with window-relative k; eval via threshold table; atomicMin.
// Grid (NWE, B), 128 threads cover all 512 outputs.
// ---------------------------------------------------------------------------
__global__ void __launch_bounds__(128) window_kernel(float* __restrict__ out) {
    __shared__ float4 sent[SENT_MAX];
    __shared__ float  sthresh[WIN + 1];
    const int W = blockIdx.x, b = blockIdx.y;
    const int tid = threadIdx.x;
    const int o = 4 * tid;

    if (tid >= 1 && tid <= WIN) {
        const float dec = expf(1.0f - (float)tid * (1.0f / TAU_F)) * (1.0f / TAU_F);
        sthresh[tid] = V_TH / dec;
    }

    const int start = g_wstart[b * (NWE + 1) + W];
    const int count = g_wstart[b * (NWE + 1) + W + 1] - start;
    const int padded = (count + CH - 1) & ~(CH - 1);
    const float kbase = (float)(W * WIN);

    const float4* __restrict__ ge = g_entries + b * ESTRIDE + start;
    for (int j = tid; j < padded; j += 128) {
        float4 e = (j < count) ? ge[j] : make_float4(1e9f, 0.f, 0.f, 0.f);
        e.x -= kbase;                       // window-relative arrival time
        sent[j] = e;
    }
    __syncthreads();

    const float2* Sp = &g_S[(b * NWE + W) * OUT_SZ + o];
    const float4 s01 = *(const float4*)(Sp);
    const float4 s23 = *(const float4*)(Sp + 2);
    float A0 = s01.x, B0 = s01.y, A1 = s01.z, B1 = s01.w;
    float A2 = s23.x, B2 = s23.y, A3 = s23.z, B3 = s23.w;

    const float4* __restrict__ wp = (const float4*)g_wT + tid;

    int t_dt = 1, cand0 = 1000, cand1 = 1000, cand2 = 1000, cand3 = 1000;
    if (count > 0) {
        float4 wc[CH];
        #pragma unroll
        for (int q = 0; q < CH; q++) wc[q] = wp[((int)sent[q].y) << 7];
        const int nch = padded / CH;
        for (int c = 0; c < nch; c++) {
            float4 wn[CH];
            if (c + 1 < nch) {
                #pragma unroll
                for (int q = 0; q < CH; q++)
                    wn[q] = wp[((int)sent[(c + 1) * CH + q].y) << 7];
            }
            #pragma unroll
            for (int q = 0; q < CH; q++) {
                const float4 e = sent[c * CH + q];
                while ((float)t_dt < e.x && t_dt <= WIN) {   // uniform across block
                    const float tf = (float)t_dt;
                    const float th = sthresh[t_dt];
                    if (fmaf(tf, A0, -B0) >= th) cand0 = min(cand0, t_dt);
                    if (fmaf(tf, A1, -B1) >= th) cand1 = min(cand1, t_dt);
                    if (fmaf(tf, A2, -B2) >= th) cand2 = min(cand2, t_dt);
                    if (fmaf(tf, A3, -B3) >= th) cand3 = min(cand3, t_dt);
                    t_dt++;
                }
                A0 = fmaf(wc[q].x, e.z, A0); B0 = fmaf(wc[q].x, e.w, B0);
                A1 = fmaf(wc[q].y, e.z, A1); B1 = fmaf(wc[q].y, e.w, B1);
                A2 = fmaf(wc[q].z, e.z, A2); B2 = fmaf(wc[q].z, e.w, B2);
                A3 = fmaf(wc[q].w, e.z, A3); B3 = fmaf(wc[q].w, e.w, B3);
            }
            #pragma unroll
            for (int q = 0; q < CH; q++) wc[q] = wn[q];
            if (__all_sync(0xffffffffu,
                           (cand0 < 1000) & (cand1 < 1000) &
                           (cand2 < 1000) & (cand3 < 1000))) break;
        }
    }
    while (t_dt <= WIN) {                                    // tail / empty window
        const float tf = (float)t_dt;
        const float th = sthresh[t_dt];
        if (fmaf(tf, A0, -B0) >= th) cand0 = min(cand0, t_dt);
        if (fmaf(tf, A1, -B1) >= th) cand1 = min(cand1, t_dt);
        if (fmaf(tf, A2, -B2) >= th) cand2 = min(cand2, t_dt);
        if (fmaf(tf, A3, -B3) >= th) cand3 = min(cand3, t_dt);
        t_dt++;
    }
    int* ob = (int*)out + b * OUT_SZ;
    if (cand0 <= WIN) atomicMin(ob + o,     __float_as_int(kbase + (float)cand0));
    if (cand1 <= WIN) atomicMin(ob + o + 1, __float_as_int(kbase + (float)cand1));
    if (cand2 <= WIN) atomicMin(ob + o + 2, __float_as_int(kbase + (float)cand2));
    if (cand3 <= WIN) atomicMin(ob + o + 3, __float_as_int(kbase + (float)cand3));
}

// ---------------------------------------------------------------------------
extern "C" void kernel_launch(void* const* d_in, const int* in_sizes, int n_in,
                              void* d_out, int out_size) {
    const float* in_spike = (const float*)d_in[0];  // [B, IN]
    const float* weight   = (const float*)d_in[1];  // [OUT, IN]
    float* out = (float*)d_out;                     // [B, OUT]
    (void)in_sizes; (void)n_in; (void)out_size;

    prep_kernel<<<B_SZ + (IN_SZ / 32) * (OUT_SZ / 32), 1024>>>(in_spike, weight, out);
    partial_kernel<<<dim3(NWE, B_SZ), 128>>>();
    scan_kernel<<<dim3(OUT_SZ / 128, B_SZ), 128>>>(out);
    window_kernel<<<dim3(NWE, B_SZ), 128>>>(out);
}